// round 8
// baseline (speedup 1.0000x reference)
#include <cuda_runtime.h>
#include <math.h>

// ---------------------------------------------------------------------------
// Problem constants
// B=2, H=W=256, C=256, CD=128, TD=128, HD=32, NH=4, WS=8, SHIFT=4
// PIX = B*H*W = 131072 pixel-tokens. All token tensors are [PIX, ch].
// ---------------------------------------------------------------------------
#define PIX 131072

// Scratch buffers (static device globals; allocation-free per harness rules)
__device__ float g_convx[(size_t)PIX * 128];   // conv path features (pixel order)
__device__ float g_r1[(size_t)PIX * 128];      // conv3x3 intermediate
__device__ float g_tw[(size_t)PIX * 128];      // trans features, window-token order
__device__ float g_h[(size_t)PIX * 128];       // layernorm output (reused ln1/ln2)
__device__ float g_qkv[(size_t)PIX * 384];     // qkv, window-token order
__device__ float g_attnout[(size_t)PIX * 128]; // attention output, window-token order
__device__ float g_t[(size_t)PIX * 128];       // transformer residual stream
__device__ float g_m1[(size_t)PIX * 512];      // mlp hidden

__device__ __forceinline__ float* sel_buf(int s) {
    switch (s) {
        case 1: return g_convx;
        case 2: return g_tw;
        case 3: return g_h;
        case 4: return g_qkv;
        case 5: return g_attnout;
        case 6: return g_t;
        case 7: return g_m1;
        case 8: return g_r1;
        default: return nullptr;
    }
}

// pixel index p = b*65536 + y*256 + x  ->  window-token index after roll(-4,-4)
// token(wi,wj,r,c) corresponds to pixel y=(wi*8+r+4)%256, x=(wj*8+c+4)%256
__device__ __forceinline__ int tok_of_pixel(int p) {
    int b = p >> 16;
    int y = (p >> 8) & 255;
    int x = p & 255;
    int i = (y + 252) & 255;  // (y-4) mod 256
    int j = (x + 252) & 255;
    int wi = i >> 3, r = i & 7;
    int wj = j >> 3, c = j & 7;
    return (((b << 10) | (wi << 5) | wj) << 6) | (r << 3) | c;
}

// ---------------------------------------------------------------------------
// Generic tiled SGEMM: C[M,N] = epilogue(A[M,K] @ W[K,N] + bias)
// BM=BN=128, BK=16, 256 threads, 8x8 per-thread micro-tile.
// gather: 0 = A rows contiguous (stride K); 1 = concat(convx[p], t[tok(p)])
// epi: 0 plain, 1 gelu, 2 +resid, 3 split->convx/tw (conv1), 4 +extra (conv2->out)
// ---------------------------------------------------------------------------
#define GA_NONE   0
#define GA_CONCAT 1
#define EPI_PLAIN 0
#define EPI_GELU  1
#define EPI_RESID 2
#define EPI_SPLIT 3
#define EPI_ADDX  4

__global__ __launch_bounds__(256) void gemm_kernel(
    const float* __restrict__ Aext, int asel,
    const float* __restrict__ W,
    const float* __restrict__ bias,
    const float* __restrict__ Rext, int rsel,
    const float* __restrict__ extra,
    float* __restrict__ Cext, int csel,
    int N, int K, int gather, int epi)
{
    const float* A = asel ? sel_buf(asel) : Aext;
    const float* R = rsel ? sel_buf(rsel) : Rext;
    float* C = csel ? sel_buf(csel) : Cext;

    __shared__ __align__(16) float As[16][132];
    __shared__ __align__(16) float Bs[16][128];

    const int bm = blockIdx.y << 7;
    const int bn = blockIdx.x << 7;
    const int tid = threadIdx.x;
    const int ty = tid >> 4, tx = tid & 15;

    float acc[8][8];
#pragma unroll
    for (int i = 0; i < 8; i++)
#pragma unroll
        for (int j = 0; j < 8; j++) acc[i][j] = 0.f;

    for (int k0 = 0; k0 < K; k0 += 16) {
        // load A tile (128 rows x 16 k), transposed into As[k][m]
#pragma unroll
        for (int l = 0; l < 2; l++) {
            int f = tid + (l << 8);
            int row = f >> 2;
            int kk4 = (f & 3) << 2;
            int m = bm + row;
            int k = k0 + kk4;
            float4 v;
            if (gather == GA_NONE) {
                v = *(const float4*)(A + (size_t)m * K + k);
            } else { // concat: k<128 -> convx[p], else t[tok(p)]
                if (k < 128) {
                    v = *(const float4*)(g_convx + (size_t)m * 128 + k);
                } else {
                    int tk = tok_of_pixel(m);
                    v = *(const float4*)(g_t + (size_t)tk * 128 + (k - 128));
                }
            }
            As[kk4 + 0][row] = v.x;
            As[kk4 + 1][row] = v.y;
            As[kk4 + 2][row] = v.z;
            As[kk4 + 3][row] = v.w;
        }
        // load B tile (16 k x 128 n)
#pragma unroll
        for (int l = 0; l < 2; l++) {
            int f = tid + (l << 8);
            int kk = f >> 5;
            int c4 = (f & 31) << 2;
            *(float4*)&Bs[kk][c4] = *(const float4*)(W + (size_t)(k0 + kk) * N + bn + c4);
        }
        __syncthreads();
#pragma unroll
        for (int kk = 0; kk < 16; kk++) {
            float4 a0 = *(const float4*)&As[kk][ty * 8];
            float4 a1 = *(const float4*)&As[kk][ty * 8 + 4];
            float4 b0 = *(const float4*)&Bs[kk][tx * 8];
            float4 b1 = *(const float4*)&Bs[kk][tx * 8 + 4];
            float a[8] = {a0.x, a0.y, a0.z, a0.w, a1.x, a1.y, a1.z, a1.w};
            float b[8] = {b0.x, b0.y, b0.z, b0.w, b1.x, b1.y, b1.z, b1.w};
#pragma unroll
            for (int i = 0; i < 8; i++)
#pragma unroll
                for (int j = 0; j < 8; j++) acc[i][j] += a[i] * b[j];
        }
        __syncthreads();
    }

    // epilogue
#pragma unroll
    for (int i = 0; i < 8; i++) {
        const int m = bm + ty * 8 + i;
        if (epi == EPI_SPLIT) {
            const size_t twbase = (size_t)tok_of_pixel(m) * 128;
#pragma unroll
            for (int j = 0; j < 8; j++) {
                const int n = bn + tx * 8 + j;
                float v = acc[i][j] + bias[n];
                if (n < 128) g_convx[(size_t)m * 128 + n] = v;
                else         g_tw[twbase + (n - 128)] = v;
            }
        } else {
#pragma unroll
            for (int j = 0; j < 8; j++) {
                const int n = bn + tx * 8 + j;
                float v = acc[i][j] + bias[n];
                const size_t idx = (size_t)m * N + n;
                if (epi == EPI_GELU) {
                    v = 0.5f * v * (1.f + erff(v * 0.70710678118654752f));
                } else if (epi == EPI_RESID) {
                    v += R[idx];
                } else if (epi == EPI_ADDX) {
                    v += extra[idx];
                }
                C[idx] = v;
            }
        }
    }
}

// ---------------------------------------------------------------------------
// 3x3 conv (SAME), implicit GEMM. 128 contiguous pixels per block (all share
// one image row since W=256), all 128 output channels. K-loop = 9 taps x 8
// chunks of 16 input channels. Epilogue: lrelu then optional +scale*resid.
// ---------------------------------------------------------------------------
__global__ __launch_bounds__(256) void conv3_kernel(
    int insel, const float* __restrict__ W,
    const float* __restrict__ bias,
    int rsel, float rscale, int osel)
{
    const float* in = sel_buf(insel);
    const float* R = rsel ? sel_buf(rsel) : nullptr;
    float* out = sel_buf(osel);

    __shared__ __align__(16) float As[16][132];
    __shared__ __align__(16) float Bs[16][128];

    const int bm = blockIdx.x << 7;
    const int b = bm >> 16;
    const int y = (bm >> 8) & 255;
    const int x0 = bm & 255;
    const int tid = threadIdx.x;
    const int ty = tid >> 4, tx = tid & 15;

    float acc[8][8];
#pragma unroll
    for (int i = 0; i < 8; i++)
#pragma unroll
        for (int j = 0; j < 8; j++) acc[i][j] = 0.f;

    for (int tap = 0; tap < 9; tap++) {
        const int dy = tap / 3 - 1;
        const int dx = tap % 3 - 1;
        const int yy = y + dy;
        const bool rowok = ((unsigned)yy < 256u);
        for (int kc = 0; kc < 128; kc += 16) {
#pragma unroll
            for (int l = 0; l < 2; l++) {
                int f = tid + (l << 8);
                int row = f >> 2;
                int kk4 = (f & 3) << 2;
                int xx = x0 + row + dx;
                float4 v = make_float4(0.f, 0.f, 0.f, 0.f);
                if (rowok && (unsigned)xx < 256u) {
                    size_t idx = ((size_t)((b * 256 + yy) * 256 + xx)) * 128 + kc + kk4;
                    v = *(const float4*)(in + idx);
                }
                As[kk4 + 0][row] = v.x;
                As[kk4 + 1][row] = v.y;
                As[kk4 + 2][row] = v.z;
                As[kk4 + 3][row] = v.w;
            }
#pragma unroll
            for (int l = 0; l < 2; l++) {
                int f = tid + (l << 8);
                int kk = f >> 5;
                int c4 = (f & 31) << 2;
                *(float4*)&Bs[kk][c4] =
                    *(const float4*)(W + (size_t)(tap * 128 + kc + kk) * 128 + c4);
            }
            __syncthreads();
#pragma unroll
            for (int kk = 0; kk < 16; kk++) {
                float4 a0 = *(const float4*)&As[kk][ty * 8];
                float4 a1 = *(const float4*)&As[kk][ty * 8 + 4];
                float4 b0 = *(const float4*)&Bs[kk][tx * 8];
                float4 b1 = *(const float4*)&Bs[kk][tx * 8 + 4];
                float a[8] = {a0.x, a0.y, a0.z, a0.w, a1.x, a1.y, a1.z, a1.w};
                float bb[8] = {b0.x, b0.y, b0.z, b0.w, b1.x, b1.y, b1.z, b1.w};
#pragma unroll
                for (int i = 0; i < 8; i++)
#pragma unroll
                    for (int j = 0; j < 8; j++) acc[i][j] += a[i] * bb[j];
            }
            __syncthreads();
        }
    }

#pragma unroll
    for (int i = 0; i < 8; i++) {
        const size_t m = (size_t)bm + ty * 8 + i;
#pragma unroll
        for (int j = 0; j < 8; j++) {
            const int n = tx * 8 + j;
            float v = acc[i][j] + bias[n];
            v = (v >= 0.f) ? v : 0.01f * v;
            if (R) v += rscale * R[m * 128 + n];
            out[m * 128 + n] = v;
        }
    }
}

// ---------------------------------------------------------------------------
// LayerNorm over 128 channels; 1 warp per row, 8 rows per block.
// ---------------------------------------------------------------------------
__global__ __launch_bounds__(256) void ln_kernel(
    int insel, const float* __restrict__ gamma,
    const float* __restrict__ beta, int osel)
{
    const float* in = sel_buf(insel);
    float* out = sel_buf(osel);
    const int row = blockIdx.x * 8 + (threadIdx.x >> 5);
    const int lane = threadIdx.x & 31;
    const float4 v = *(const float4*)(in + (size_t)row * 128 + lane * 4);
    float sum = v.x + v.y + v.z + v.w;
    float sq = v.x * v.x + v.y * v.y + v.z * v.z + v.w * v.w;
#pragma unroll
    for (int off = 16; off > 0; off >>= 1) {
        sum += __shfl_xor_sync(0xffffffffu, sum, off);
        sq  += __shfl_xor_sync(0xffffffffu, sq, off);
    }
    const float mean = sum * 0.0078125f;
    const float var = sq * 0.0078125f - mean * mean;
    const float rstd = rsqrtf(var + 1e-5f);
    const float4 g4 = *(const float4*)(gamma + lane * 4);
    const float4 b4 = *(const float4*)(beta + lane * 4);
    float4 o;
    o.x = (v.x - mean) * rstd * g4.x + b4.x;
    o.y = (v.y - mean) * rstd * g4.y + b4.y;
    o.z = (v.z - mean) * rstd * g4.z + b4.z;
    o.w = (v.w - mean) * rstd * g4.w + b4.w;
    *(float4*)(out + (size_t)row * 128 + lane * 4) = o;
}

// ---------------------------------------------------------------------------
// Windowed attention: 1 block per (batch, window) = 2048 blocks, 256 threads.
// Thread t handles (head = t/64, query = t%64). Scores/softmax in registers;
// K then V staged through the same smem buffer (two phases).
// ---------------------------------------------------------------------------
__global__ __launch_bounds__(256) void attn_kernel(const float* __restrict__ rpb)
{
    __shared__ __align__(16) float skv[64][128];
    __shared__ float srpb[900];

    const int wid = blockIdx.x;          // b*1024 + wi*32 + wj
    const int wi = (wid >> 5) & 31;
    const int wj = wid & 31;
    const size_t tokbase = (size_t)wid * 64;
    const float* qkvp = g_qkv + tokbase * 384;
    const int tid = threadIdx.x;

    // load K (cols 128..255 of qkv)
#pragma unroll
    for (int l = 0; l < 8; l++) {
        int f = tid + (l << 8);
        int j = f >> 5;
        int c4 = (f & 31) << 2;
        *(float4*)&skv[j][c4] = *(const float4*)(qkvp + (size_t)j * 384 + 128 + c4);
    }
    for (int f = tid; f < 900; f += 256) srpb[f] = rpb[f];
    __syncthreads();

    const int head = tid >> 6;
    const int i = tid & 63;
    const int hb = head << 5;

    float q[32];
    {
        const float* qp = qkvp + (size_t)i * 384 + hb;
#pragma unroll
        for (int d4 = 0; d4 < 8; d4++) {
            float4 v = *(const float4*)(qp + 4 * d4);
            q[4 * d4 + 0] = v.x; q[4 * d4 + 1] = v.y;
            q[4 * d4 + 2] = v.z; q[4 * d4 + 3] = v.w;
        }
    }
    const int ri = i >> 3, ci = i & 7;
    const int gi = ((wi == 31) ? (ri < 4 ? 1 : 2) : 0) * 3
                 + ((wj == 31) ? (ci < 4 ? 1 : 2) : 0);

    float s[64];
#pragma unroll
    for (int j = 0; j < 64; j++) {
        float dot = 0.f;
#pragma unroll
        for (int d4 = 0; d4 < 8; d4++) {
            float4 kv = *(const float4*)&skv[j][hb + 4 * d4];
            dot += q[4 * d4 + 0] * kv.x;
            dot += q[4 * d4 + 1] * kv.y;
            dot += q[4 * d4 + 2] * kv.z;
            dot += q[4 * d4 + 3] * kv.w;
        }
        const int rj = j >> 3, cj = j & 7;
        const int gj = ((wi == 31) ? (rj < 4 ? 1 : 2) : 0) * 3
                     + ((wj == 31) ? (cj < 4 ? 1 : 2) : 0);
        const float bias = srpb[((ri - rj + 7) * 15 + (ci - cj + 7)) * 4 + head];
        const float msk = (gi == gj) ? 0.f : -1000000000.f;
        s[j] = dot * 0.17677669529663689f + bias + msk;
    }

    float mx = s[0];
#pragma unroll
    for (int j = 1; j < 64; j++) mx = fmaxf(mx, s[j]);
    float sum = 0.f;
#pragma unroll
    for (int j = 0; j < 64; j++) { s[j] = __expf(s[j] - mx); sum += s[j]; }
    const float inv = 1.f / sum;

    __syncthreads();  // all threads done reading K
    // load V (cols 256..383)
#pragma unroll
    for (int l = 0; l < 8; l++) {
        int f = tid + (l << 8);
        int j = f >> 5;
        int c4 = (f & 31) << 2;
        *(float4*)&skv[j][c4] = *(const float4*)(qkvp + (size_t)j * 384 + 256 + c4);
    }
    __syncthreads();

    float o[32];
#pragma unroll
    for (int d = 0; d < 32; d++) o[d] = 0.f;
#pragma unroll
    for (int j = 0; j < 64; j++) {
        const float a = s[j];
#pragma unroll
        for (int d4 = 0; d4 < 8; d4++) {
            float4 vv = *(const float4*)&skv[j][hb + 4 * d4];
            o[4 * d4 + 0] += a * vv.x;
            o[4 * d4 + 1] += a * vv.y;
            o[4 * d4 + 2] += a * vv.z;
            o[4 * d4 + 3] += a * vv.w;
        }
    }
    float* op = g_attnout + (tokbase + i) * 128 + hb;
#pragma unroll
    for (int d4 = 0; d4 < 8; d4++) {
        float4 v = make_float4(o[4 * d4 + 0] * inv, o[4 * d4 + 1] * inv,
                               o[4 * d4 + 2] * inv, o[4 * d4 + 3] * inv);
        *(float4*)(op + 4 * d4) = v;
    }
}

// ---------------------------------------------------------------------------
// Launch orchestration
// ---------------------------------------------------------------------------
extern "C" void kernel_launch(void* const* d_in, const int* in_sizes, int n_in,
                              void* d_out, int out_size)
{
    (void)in_sizes; (void)n_in; (void)out_size;
    const float* x    = (const float*)d_in[0];
    const float* c1w  = (const float*)d_in[1];
    const float* c1b  = (const float*)d_in[2];
    const float* rw1  = (const float*)d_in[3];
    const float* rb1  = (const float*)d_in[4];
    const float* rw2  = (const float*)d_in[5];
    const float* rb2  = (const float*)d_in[6];
    const float* ln1g = (const float*)d_in[7];
    const float* ln1b = (const float*)d_in[8];
    const float* qkvw = (const float*)d_in[9];
    const float* qkvb = (const float*)d_in[10];
    const float* rpb  = (const float*)d_in[11];
    const float* pw   = (const float*)d_in[12];
    const float* pb   = (const float*)d_in[13];
    const float* ln2g = (const float*)d_in[14];
    const float* ln2b = (const float*)d_in[15];
    const float* mw1  = (const float*)d_in[16];
    const float* mb1  = (const float*)d_in[17];
    const float* mw2  = (const float*)d_in[18];
    const float* mb2  = (const float*)d_in[19];
    const float* c2w  = (const float*)d_in[20];
    const float* c2b  = (const float*)d_in[21];
    float* out = (float*)d_out;

    const dim3 blk(256);
    const int MB = PIX / 128;  // 1024 M-tiles

    // 1. conv1 (1x1): y = x @ c1w + c1b; split -> g_convx (pixel order),
    //    g_tw (window-token order, rolled by -SHIFT)
    gemm_kernel<<<dim3(2, MB), blk>>>(x, 0, c1w, c1b, nullptr, 0, nullptr,
                                      nullptr, 0, 256, 256, GA_NONE, EPI_SPLIT);
    // 2. r1 = lrelu(conv3x3(convx, rw1) + rb1)
    conv3_kernel<<<MB, blk>>>(1, rw1, rb1, 0, 0.f, 8);
    // 3. convx = lrelu(conv3x3(r1, rw2) + rb2) + 2*convx   (in-place residual)
    conv3_kernel<<<MB, blk>>>(8, rw2, rb2, 1, 2.f, 1);
    // 4. h = LN1(tw)
    ln_kernel<<<PIX / 8, blk>>>(2, ln1g, ln1b, 3);
    // 5. qkv = h @ qkvw + qkvb
    gemm_kernel<<<dim3(3, MB), blk>>>(nullptr, 3, qkvw, qkvb, nullptr, 0, nullptr,
                                      nullptr, 4, 384, 128, GA_NONE, EPI_PLAIN);
    // 6. windowed attention -> g_attnout
    attn_kernel<<<2048, blk>>>(rpb);
    // 7. t = attnout @ pw + pb + tw
    gemm_kernel<<<dim3(1, MB), blk>>>(nullptr, 5, pw, pb, nullptr, 2, nullptr,
                                      nullptr, 6, 128, 128, GA_NONE, EPI_RESID);
    // 8. h = LN2(t)
    ln_kernel<<<PIX / 8, blk>>>(6, ln2g, ln2b, 3);
    // 9. m1 = gelu(h @ mw1 + mb1)
    gemm_kernel<<<dim3(4, MB), blk>>>(nullptr, 3, mw1, mb1, nullptr, 0, nullptr,
                                      nullptr, 7, 512, 128, GA_NONE, EPI_GELU);
    // 10. t = m1 @ mw2 + mb2 + t   (in-place, element-wise 1:1, safe)
    gemm_kernel<<<dim3(1, MB), blk>>>(nullptr, 7, mw2, mb2, nullptr, 6, nullptr,
                                      nullptr, 6, 128, 512, GA_NONE, EPI_RESID);
    // 11. out = concat(convx, t[tok(p)]) @ c2w + c2b + x
    gemm_kernel<<<dim3(2, MB), blk>>>(nullptr, 0, c2w, c2b, nullptr, 0, x,
                                      out, 0, 256, 256, GA_CONCAT, EPI_ADDX);
}

// round 13
// speedup vs baseline: 2.6023x; 2.6023x over previous
#include <cuda_runtime.h>
#include <math.h>

// ---------------------------------------------------------------------------
// Problem constants
// B=2, H=W=256, C=256, CD=128, TD=128, HD=32, NH=4, WS=8, SHIFT=4
// PIX = B*H*W = 131072 pixel-tokens. All token tensors are [PIX, ch].
// ---------------------------------------------------------------------------
#define PIX 131072

// Scratch buffers (static device globals; allocation-free per harness rules)
__device__ float g_convx[(size_t)PIX * 128];   // conv path features (pixel order)
__device__ float g_r1[(size_t)PIX * 128];      // conv3x3 intermediate
__device__ float g_tw[(size_t)PIX * 128];      // trans features, window-token order
__device__ float g_h[(size_t)PIX * 128];       // layernorm output (reused ln1/ln2)
__device__ float g_qkv[(size_t)PIX * 384];     // qkv, window-token order
__device__ float g_attnout[(size_t)PIX * 128]; // attention output, window-token order
__device__ float g_t[(size_t)PIX * 128];       // transformer residual stream
__device__ float g_m1[(size_t)PIX * 512];      // mlp hidden

__device__ __forceinline__ float* sel_buf(int s) {
    switch (s) {
        case 1: return g_convx;
        case 2: return g_tw;
        case 3: return g_h;
        case 4: return g_qkv;
        case 5: return g_attnout;
        case 6: return g_t;
        case 7: return g_m1;
        case 8: return g_r1;
        default: return nullptr;
    }
}

// pixel index p = b*65536 + y*256 + x  ->  window-token index after roll(-4,-4)
__device__ __forceinline__ int tok_of_pixel(int p) {
    int b = p >> 16;
    int y = (p >> 8) & 255;
    int x = p & 255;
    int i = (y + 252) & 255;  // (y-4) mod 256
    int j = (x + 252) & 255;
    int wi = i >> 3, r = i & 7;
    int wj = j >> 3, c = j & 7;
    return (((b << 10) | (wi << 5) | wj) << 6) | (r << 3) | c;
}

// ---------------------------------------------------------------------------
// TF32 tensor-core building blocks
// ---------------------------------------------------------------------------
__device__ __forceinline__ unsigned f2tf(float f) {
    unsigned u;
    asm("cvt.rna.tf32.f32 %0, %1;" : "=r"(u) : "f"(f));
    return u;
}

__device__ __forceinline__ void mma8(float* c, const unsigned* a, const unsigned* b) {
    asm volatile(
        "mma.sync.aligned.m16n8k8.row.col.f32.tf32.tf32.f32 "
        "{%0,%1,%2,%3},{%4,%5,%6,%7},{%8,%9},{%0,%1,%2,%3};"
        : "+f"(c[0]), "+f"(c[1]), "+f"(c[2]), "+f"(c[3])
        : "r"(a[0]), "r"(a[1]), "r"(a[2]), "r"(a[3]),
          "r"(b[0]), "r"(b[1]));
}

// smem layout for a 128x16 tf32 tile:
//   idx = gh*552 + q*136 + col,  gh = (k%16)/4 packs (k-group, k-half),
//   q = k%4, col = m or n.  552 ≡ 8, 136 ≡ 8 (mod 32) -> both the fragment
//   LDS reads and the transpose STS scatter are 32-bank conflict-free.
#define QP 136
#define GHP 552
#define STILE 2208

// ---------------------------------------------------------------------------
// Generic tiled TF32 GEMM: C[M,N] = epilogue(A[M,K] @ W[K,N] + bias)
// BM=BN=128, BK=16, 256 threads (8 warps, 32x64 warp tiles of m16n8k8 frags).
// ---------------------------------------------------------------------------
#define GA_NONE   0
#define GA_CONCAT 1
#define EPI_PLAIN 0
#define EPI_GELU  1
#define EPI_RESID 2
#define EPI_SPLIT 3
#define EPI_ADDX  4

__global__ __launch_bounds__(256, 2) void gemm_mma(
    const float* __restrict__ Aext, int asel,
    const float* __restrict__ W,
    const float* __restrict__ bias,
    int rsel,
    const float* __restrict__ extra,
    float* __restrict__ Cext, int csel,
    int N, int K, int gather, int epi)
{
    const float* A = asel ? sel_buf(asel) : Aext;
    const float* R = rsel ? sel_buf(rsel) : nullptr;
    float* C = csel ? sel_buf(csel) : Cext;

    __shared__ __align__(16) float As[STILE];
    __shared__ __align__(16) float Bs[STILE];

    const int bm = (int)blockIdx.y << 7;
    const int bn = (int)blockIdx.x << 7;
    const int tid = threadIdx.x;
    const int warp = tid >> 5, lane = tid & 31;
    const int gid = lane >> 2, t4 = lane & 3;
    const int wm = (warp >> 1) << 5;   // 0,32,64,96
    const int wn = (warp & 1) << 6;    // 0,64

    // global-load indices
    const int arow = tid >> 2;            // 0..63 (+64 for l=1)
    const int akk4 = (tid & 3) << 2;      // 0,4,8,12
    const int bkk  = tid >> 5;            // 0..7 (+8 for l=1)
    const int bc4  = (tid & 31) << 2;     // 0..124

    float acc[2][8][4];
#pragma unroll
    for (int mt = 0; mt < 2; mt++)
#pragma unroll
        for (int nt = 0; nt < 8; nt++)
#pragma unroll
            for (int e = 0; e < 4; e++) acc[mt][nt][e] = 0.f;

    float4 pa[2], pb[2];

    auto loadA = [&](int k0, int l) -> float4 {
        const int m = bm + arow + (l << 6);
        const int k = k0 + akk4;
        if (gather == GA_CONCAT) {
            if (k < 128) return *(const float4*)(g_convx + (size_t)m * 128 + k);
            const int tk = tok_of_pixel(m);
            return *(const float4*)(g_t + (size_t)tk * 128 + (k - 128));
        }
        return *(const float4*)(A + (size_t)m * K + k);
    };
    auto loadB = [&](int k0, int l) -> float4 {
        const int kk = bkk + (l << 3);
        return *(const float4*)(W + (size_t)(k0 + kk) * N + bn + bc4);
    };
    auto stA = [&](float4 v, int l) {
        float* p = As + (akk4 >> 2) * GHP + arow + (l << 6);
        p[0 * QP] = __uint_as_float(f2tf(v.x));
        p[1 * QP] = __uint_as_float(f2tf(v.y));
        p[2 * QP] = __uint_as_float(f2tf(v.z));
        p[3 * QP] = __uint_as_float(f2tf(v.w));
    };
    auto stB = [&](float4 v, int l) {
        const int kk = bkk + (l << 3);
        float4 c;
        c.x = __uint_as_float(f2tf(v.x));
        c.y = __uint_as_float(f2tf(v.y));
        c.z = __uint_as_float(f2tf(v.z));
        c.w = __uint_as_float(f2tf(v.w));
        *(float4*)(Bs + (kk >> 2) * GHP + (kk & 3) * QP + bc4) = c;
    };
    auto compute = [&]() {
#pragma unroll
        for (int g = 0; g < 2; g++) {
            unsigned a[2][4];
#pragma unroll
            for (int mt = 0; mt < 2; mt++) {
                const float* p0 = As + (2 * g + 0) * GHP + t4 * QP + wm + mt * 16 + gid;
                const float* p1 = As + (2 * g + 1) * GHP + t4 * QP + wm + mt * 16 + gid;
                a[mt][0] = __float_as_uint(p0[0]);
                a[mt][1] = __float_as_uint(p0[8]);
                a[mt][2] = __float_as_uint(p1[0]);
                a[mt][3] = __float_as_uint(p1[8]);
            }
            unsigned b[8][2];
#pragma unroll
            for (int nt = 0; nt < 8; nt++) {
                const int n = wn + nt * 8 + gid;
                b[nt][0] = __float_as_uint(Bs[(2 * g + 0) * GHP + t4 * QP + n]);
                b[nt][1] = __float_as_uint(Bs[(2 * g + 1) * GHP + t4 * QP + n]);
            }
#pragma unroll
            for (int mt = 0; mt < 2; mt++)
#pragma unroll
                for (int nt = 0; nt < 8; nt++)
                    mma8(acc[mt][nt], a[mt], b[nt]);
        }
    };

    pa[0] = loadA(0, 0); pa[1] = loadA(0, 1);
    pb[0] = loadB(0, 0); pb[1] = loadB(0, 1);
    for (int k0 = 0; k0 < K; k0 += 16) {
        stA(pa[0], 0); stA(pa[1], 1);
        stB(pb[0], 0); stB(pb[1], 1);
        __syncthreads();
        const int kn = k0 + 16;
        if (kn < K) {
            pa[0] = loadA(kn, 0); pa[1] = loadA(kn, 1);
            pb[0] = loadB(kn, 0); pb[1] = loadB(kn, 1);
        }
        compute();
        __syncthreads();
    }

    // ---- epilogue ----
    float2 bb[8];
#pragma unroll
    for (int nt = 0; nt < 8; nt++)
        bb[nt] = *(const float2*)(bias + bn + wn + nt * 8 + t4 * 2);

#pragma unroll
    for (int mt = 0; mt < 2; mt++) {
#pragma unroll
        for (int h = 0; h < 2; h++) {
            const int m = bm + wm + mt * 16 + gid + h * 8;
            if (epi == EPI_SPLIT) {
                float* op = (bn == 0) ? (g_convx + (size_t)m * 128)
                                      : (g_tw + (size_t)tok_of_pixel(m) * 128);
#pragma unroll
                for (int nt = 0; nt < 8; nt++) {
                    const int col = wn + nt * 8 + t4 * 2;
                    float2 v;
                    v.x = acc[mt][nt][h * 2 + 0] + bb[nt].x;
                    v.y = acc[mt][nt][h * 2 + 1] + bb[nt].y;
                    *(float2*)(op + col) = v;
                }
            } else {
                const size_t base = (size_t)m * N + bn + wn;
#pragma unroll
                for (int nt = 0; nt < 8; nt++) {
                    const int off = nt * 8 + t4 * 2;
                    float vx = acc[mt][nt][h * 2 + 0] + bb[nt].x;
                    float vy = acc[mt][nt][h * 2 + 1] + bb[nt].y;
                    if (epi == EPI_GELU) {
                        vx = 0.5f * vx * (1.f + erff(vx * 0.70710678118654752f));
                        vy = 0.5f * vy * (1.f + erff(vy * 0.70710678118654752f));
                    } else if (epi == EPI_RESID) {
                        const float2 r = *(const float2*)(R + base + off);
                        vx += r.x; vy += r.y;
                    } else if (epi == EPI_ADDX) {
                        const float2 r = *(const float2*)(extra + base + off);
                        vx += r.x; vy += r.y;
                    }
                    float2 v; v.x = vx; v.y = vy;
                    *(float2*)(C + base + off) = v;
                }
            }
        }
    }
}

// ---------------------------------------------------------------------------
// 3x3 conv (SAME) on TF32 tensor cores. Implicit GEMM: 128 contiguous pixels
// per block (one image row), K-loop = 9 taps x 8 chunks of 16 in-channels.
// Epilogue: lrelu then optional +scale*resid.
// ---------------------------------------------------------------------------
__global__ __launch_bounds__(256, 2) void conv3_mma(
    int insel, const float* __restrict__ W,
    const float* __restrict__ bias,
    int rsel, float rscale, int osel)
{
    const float* in = sel_buf(insel);
    const float* R = rsel ? sel_buf(rsel) : nullptr;
    float* out = sel_buf(osel);

    __shared__ __align__(16) float As[STILE];
    __shared__ __align__(16) float Bs[STILE];

    const int bm = (int)blockIdx.x << 7;
    const int b = bm >> 16;
    const int y = (bm >> 8) & 255;
    const int x0 = bm & 255;
    const int tid = threadIdx.x;
    const int warp = tid >> 5, lane = tid & 31;
    const int gid = lane >> 2, t4 = lane & 3;
    const int wm = (warp >> 1) << 5;
    const int wn = (warp & 1) << 6;

    const int arow = tid >> 2;
    const int akk4 = (tid & 3) << 2;
    const int bkk  = tid >> 5;
    const int bc4  = (tid & 31) << 2;

    float acc[2][8][4];
#pragma unroll
    for (int mt = 0; mt < 2; mt++)
#pragma unroll
        for (int nt = 0; nt < 8; nt++)
#pragma unroll
            for (int e = 0; e < 4; e++) acc[mt][nt][e] = 0.f;

    float4 pa[2], pb[2];

    auto loadA = [&](int it, int l) -> float4 {
        const int tap = it >> 3;
        const int kc = (it & 7) << 4;
        const int dy = tap / 3 - 1;
        const int dx = tap % 3 - 1;
        const int yy = y + dy;
        const int xx = x0 + arow + (l << 6) + dx;
        float4 v = make_float4(0.f, 0.f, 0.f, 0.f);
        if ((unsigned)yy < 256u && (unsigned)xx < 256u)
            v = *(const float4*)(in + ((size_t)((b * 256 + yy) * 256 + xx)) * 128 + kc + akk4);
        return v;
    };
    auto loadB = [&](int it, int l) -> float4 {
        const int tap = it >> 3;
        const int kc = (it & 7) << 4;
        const int kk = bkk + (l << 3);
        return *(const float4*)(W + (size_t)(tap * 128 + kc + kk) * 128 + bc4);
    };
    auto stA = [&](float4 v, int l) {
        float* p = As + (akk4 >> 2) * GHP + arow + (l << 6);
        p[0 * QP] = __uint_as_float(f2tf(v.x));
        p[1 * QP] = __uint_as_float(f2tf(v.y));
        p[2 * QP] = __uint_as_float(f2tf(v.z));
        p[3 * QP] = __uint_as_float(f2tf(v.w));
    };
    auto stB = [&](float4 v, int l) {
        const int kk = bkk + (l << 3);
        float4 c;
        c.x = __uint_as_float(f2tf(v.x));
        c.y = __uint_as_float(f2tf(v.y));
        c.z = __uint_as_float(f2tf(v.z));
        c.w = __uint_as_float(f2tf(v.w));
        *(float4*)(Bs + (kk >> 2) * GHP + (kk & 3) * QP + bc4) = c;
    };
    auto compute = [&]() {
#pragma unroll
        for (int g = 0; g < 2; g++) {
            unsigned a[2][4];
#pragma unroll
            for (int mt = 0; mt < 2; mt++) {
                const float* p0 = As + (2 * g + 0) * GHP + t4 * QP + wm + mt * 16 + gid;
                const float* p1 = As + (2 * g + 1) * GHP + t4 * QP + wm + mt * 16 + gid;
                a[mt][0] = __float_as_uint(p0[0]);
                a[mt][1] = __float_as_uint(p0[8]);
                a[mt][2] = __float_as_uint(p1[0]);
                a[mt][3] = __float_as_uint(p1[8]);
            }
            unsigned bf[8][2];
#pragma unroll
            for (int nt = 0; nt < 8; nt++) {
                const int n = wn + nt * 8 + gid;
                bf[nt][0] = __float_as_uint(Bs[(2 * g + 0) * GHP + t4 * QP + n]);
                bf[nt][1] = __float_as_uint(Bs[(2 * g + 1) * GHP + t4 * QP + n]);
            }
#pragma unroll
            for (int mt = 0; mt < 2; mt++)
#pragma unroll
                for (int nt = 0; nt < 8; nt++)
                    mma8(acc[mt][nt], a[mt], bf[nt]);
        }
    };

    pa[0] = loadA(0, 0); pa[1] = loadA(0, 1);
    pb[0] = loadB(0, 0); pb[1] = loadB(0, 1);
    for (int it = 0; it < 72; it++) {
        stA(pa[0], 0); stA(pa[1], 1);
        stB(pb[0], 0); stB(pb[1], 1);
        __syncthreads();
        if (it + 1 < 72) {
            pa[0] = loadA(it + 1, 0); pa[1] = loadA(it + 1, 1);
            pb[0] = loadB(it + 1, 0); pb[1] = loadB(it + 1, 1);
        }
        compute();
        __syncthreads();
    }

    float2 bb[8];
#pragma unroll
    for (int nt = 0; nt < 8; nt++)
        bb[nt] = *(const float2*)(bias + wn + nt * 8 + t4 * 2);

#pragma unroll
    for (int mt = 0; mt < 2; mt++) {
#pragma unroll
        for (int h = 0; h < 2; h++) {
            const size_t m = (size_t)bm + wm + mt * 16 + gid + h * 8;
#pragma unroll
            for (int nt = 0; nt < 8; nt++) {
                const int n = wn + nt * 8 + t4 * 2;
                float vx = acc[mt][nt][h * 2 + 0] + bb[nt].x;
                float vy = acc[mt][nt][h * 2 + 1] + bb[nt].y;
                vx = (vx >= 0.f) ? vx : 0.01f * vx;
                vy = (vy >= 0.f) ? vy : 0.01f * vy;
                if (R) {
                    const float2 r = *(const float2*)(R + m * 128 + n);
                    vx += rscale * r.x; vy += rscale * r.y;
                }
                float2 v; v.x = vx; v.y = vy;
                *(float2*)(out + m * 128 + n) = v;
            }
        }
    }
}

// ---------------------------------------------------------------------------
// LayerNorm over 128 channels; 1 warp per row, 8 rows per block.
// ---------------------------------------------------------------------------
__global__ __launch_bounds__(256) void ln_kernel(
    int insel, const float* __restrict__ gamma,
    const float* __restrict__ beta, int osel)
{
    const float* in = sel_buf(insel);
    float* out = sel_buf(osel);
    const int row = blockIdx.x * 8 + (threadIdx.x >> 5);
    const int lane = threadIdx.x & 31;
    const float4 v = *(const float4*)(in + (size_t)row * 128 + lane * 4);
    float sum = v.x + v.y + v.z + v.w;
    float sq = v.x * v.x + v.y * v.y + v.z * v.z + v.w * v.w;
#pragma unroll
    for (int off = 16; off > 0; off >>= 1) {
        sum += __shfl_xor_sync(0xffffffffu, sum, off);
        sq  += __shfl_xor_sync(0xffffffffu, sq, off);
    }
    const float mean = sum * 0.0078125f;
    const float var = sq * 0.0078125f - mean * mean;
    const float rstd = rsqrtf(var + 1e-5f);
    const float4 g4 = *(const float4*)(gamma + lane * 4);
    const float4 b4 = *(const float4*)(beta + lane * 4);
    float4 o;
    o.x = (v.x - mean) * rstd * g4.x + b4.x;
    o.y = (v.y - mean) * rstd * g4.y + b4.y;
    o.z = (v.z - mean) * rstd * g4.z + b4.z;
    o.w = (v.w - mean) * rstd * g4.w + b4.w;
    *(float4*)(out + (size_t)row * 128 + lane * 4) = o;
}

// ---------------------------------------------------------------------------
// Windowed attention: 1 block per (batch, window) = 2048 blocks, 256 threads.
// ---------------------------------------------------------------------------
__global__ __launch_bounds__(256) void attn_kernel(const float* __restrict__ rpb)
{
    __shared__ __align__(16) float skv[64][128];
    __shared__ float srpb[900];

    const int wid = blockIdx.x;          // b*1024 + wi*32 + wj
    const int wi = (wid >> 5) & 31;
    const int wj = wid & 31;
    const size_t tokbase = (size_t)wid * 64;
    const float* qkvp = g_qkv + tokbase * 384;
    const int tid = threadIdx.x;

#pragma unroll
    for (int l = 0; l < 8; l++) {
        int f = tid + (l << 8);
        int j = f >> 5;
        int c4 = (f & 31) << 2;
        *(float4*)&skv[j][c4] = *(const float4*)(qkvp + (size_t)j * 384 + 128 + c4);
    }
    for (int f = tid; f < 900; f += 256) srpb[f] = rpb[f];
    __syncthreads();

    const int head = tid >> 6;
    const int i = tid & 63;
    const int hb = head << 5;

    float q[32];
    {
        const float* qp = qkvp + (size_t)i * 384 + hb;
#pragma unroll
        for (int d4 = 0; d4 < 8; d4++) {
            float4 v = *(const float4*)(qp + 4 * d4);
            q[4 * d4 + 0] = v.x; q[4 * d4 + 1] = v.y;
            q[4 * d4 + 2] = v.z; q[4 * d4 + 3] = v.w;
        }
    }
    const int ri = i >> 3, ci = i & 7;
    const int gi = ((wi == 31) ? (ri < 4 ? 1 : 2) : 0) * 3
                 + ((wj == 31) ? (ci < 4 ? 1 : 2) : 0);

    float s[64];
#pragma unroll
    for (int j = 0; j < 64; j++) {
        float dot = 0.f;
#pragma unroll
        for (int d4 = 0; d4 < 8; d4++) {
            float4 kv = *(const float4*)&skv[j][hb + 4 * d4];
            dot += q[4 * d4 + 0] * kv.x;
            dot += q[4 * d4 + 1] * kv.y;
            dot += q[4 * d4 + 2] * kv.z;
            dot += q[4 * d4 + 3] * kv.w;
        }
        const int rj = j >> 3, cj = j & 7;
        const int gj = ((wi == 31) ? (rj < 4 ? 1 : 2) : 0) * 3
                     + ((wj == 31) ? (cj < 4 ? 1 : 2) : 0);
        const float bias = srpb[((ri - rj + 7) * 15 + (ci - cj + 7)) * 4 + head];
        const float msk = (gi == gj) ? 0.f : -1000000000.f;
        s[j] = dot * 0.17677669529663689f + bias + msk;
    }

    float mx = s[0];
#pragma unroll
    for (int j = 1; j < 64; j++) mx = fmaxf(mx, s[j]);
    float sum = 0.f;
#pragma unroll
    for (int j = 0; j < 64; j++) { s[j] = __expf(s[j] - mx); sum += s[j]; }
    const float inv = 1.f / sum;

    __syncthreads();  // all threads done reading K
#pragma unroll
    for (int l = 0; l < 8; l++) {
        int f = tid + (l << 8);
        int j = f >> 5;
        int c4 = (f & 31) << 2;
        *(float4*)&skv[j][c4] = *(const float4*)(qkvp + (size_t)j * 384 + 256 + c4);
    }
    __syncthreads();

    float o[32];
#pragma unroll
    for (int d = 0; d < 32; d++) o[d] = 0.f;
#pragma unroll
    for (int j = 0; j < 64; j++) {
        const float a = s[j];
#pragma unroll
        for (int d4 = 0; d4 < 8; d4++) {
            float4 vv = *(const float4*)&skv[j][hb + 4 * d4];
            o[4 * d4 + 0] += a * vv.x;
            o[4 * d4 + 1] += a * vv.y;
            o[4 * d4 + 2] += a * vv.z;
            o[4 * d4 + 3] += a * vv.w;
        }
    }
    float* op = g_attnout + (tokbase + i) * 128 + hb;
#pragma unroll
    for (int d4 = 0; d4 < 8; d4++) {
        float4 v = make_float4(o[4 * d4 + 0] * inv, o[4 * d4 + 1] * inv,
                               o[4 * d4 + 2] * inv, o[4 * d4 + 3] * inv);
        *(float4*)(op + 4 * d4) = v;
    }
}

// ---------------------------------------------------------------------------
// Launch orchestration
// ---------------------------------------------------------------------------
extern "C" void kernel_launch(void* const* d_in, const int* in_sizes, int n_in,
                              void* d_out, int out_size)
{
    (void)in_sizes; (void)n_in; (void)out_size;
    const float* x    = (const float*)d_in[0];
    const float* c1w  = (const float*)d_in[1];
    const float* c1b  = (const float*)d_in[2];
    const float* rw1  = (const float*)d_in[3];
    const float* rb1  = (const float*)d_in[4];
    const float* rw2  = (const float*)d_in[5];
    const float* rb2  = (const float*)d_in[6];
    const float* ln1g = (const float*)d_in[7];
    const float* ln1b = (const float*)d_in[8];
    const float* qkvw = (const float*)d_in[9];
    const float* qkvb = (const float*)d_in[10];
    const float* rpb  = (const float*)d_in[11];
    const float* pw   = (const float*)d_in[12];
    const float* pb   = (const float*)d_in[13];
    const float* ln2g = (const float*)d_in[14];
    const float* ln2b = (const float*)d_in[15];
    const float* mw1  = (const float*)d_in[16];
    const float* mb1  = (const float*)d_in[17];
    const float* mw2  = (const float*)d_in[18];
    const float* mb2  = (const float*)d_in[19];
    const float* c2w  = (const float*)d_in[20];
    const float* c2b  = (const float*)d_in[21];
    float* out = (float*)d_out;

    const dim3 blk(256);
    const int MB = PIX / 128;  // 1024 M-tiles

    // 1. conv1 (1x1): split -> g_convx (pixel order), g_tw (window-token order)
    gemm_mma<<<dim3(2, MB), blk>>>(x, 0, c1w, c1b, 0, nullptr,
                                   nullptr, 0, 256, 256, GA_NONE, EPI_SPLIT);
    // 2. r1 = lrelu(conv3x3(convx, rw1) + rb1)
    conv3_mma<<<MB, blk>>>(1, rw1, rb1, 0, 0.f, 8);
    // 3. convx = lrelu(conv3x3(r1, rw2) + rb2) + 2*convx
    conv3_mma<<<MB, blk>>>(8, rw2, rb2, 1, 2.f, 1);
    // 4. h = LN1(tw)
    ln_kernel<<<PIX / 8, blk>>>(2, ln1g, ln1b, 3);
    // 5. qkv = h @ qkvw + qkvb
    gemm_mma<<<dim3(3, MB), blk>>>(nullptr, 3, qkvw, qkvb, 0, nullptr,
                                   nullptr, 4, 384, 128, GA_NONE, EPI_PLAIN);
    // 6. windowed attention -> g_attnout
    attn_kernel<<<2048, blk>>>(rpb);
    // 7. t = attnout @ pw + pb + tw
    gemm_mma<<<dim3(1, MB), blk>>>(nullptr, 5, pw, pb, 2, nullptr,
                                   nullptr, 6, 128, 128, GA_NONE, EPI_RESID);
    // 8. h = LN2(t)
    ln_kernel<<<PIX / 8, blk>>>(6, ln2g, ln2b, 3);
    // 9. m1 = gelu(h @ mw1 + mb1)
    gemm_mma<<<dim3(4, MB), blk>>>(nullptr, 3, mw1, mb1, 0, nullptr,
                                   nullptr, 7, 512, 128, GA_NONE, EPI_GELU);
    // 10. t = m1 @ mw2 + mb2 + t   (in-place, element-wise 1:1, safe)
    gemm_mma<<<dim3(1, MB), blk>>>(nullptr, 7, mw2, mb2, 6, nullptr,
                                   nullptr, 6, 128, 512, GA_NONE, EPI_RESID);
    // 11. out = concat(convx, t[tok(p)]) @ c2w + c2b + x
    gemm_mma<<<dim3(2, MB), blk>>>(nullptr, 0, c2w, c2b, 0, x,
                                   out, 0, 256, 256, GA_CONCAT, EPI_ADDX);
}